// round 4
// baseline (speedup 1.0000x reference)
#include <cuda_runtime.h>

// ---------------- problem constants ----------------
#define BATCH 8
#define HP 256         // 16*16 positions
#define HR 128         // high-res H=W
#define NOUT 4928      // hyper-net param channels

typedef unsigned long long ull;

// ---------------- packed fp32 helpers ----------------
__device__ __forceinline__ ull pack2(float lo, float hi) {
    ull r; asm("mov.b64 %0, {%1, %2};" : "=l"(r) : "f"(lo), "f"(hi)); return r;
}
__device__ __forceinline__ void unpack2(ull v, float& lo, float& hi) {
    asm("mov.b64 {%0, %1}, %2;" : "=f"(lo), "=f"(hi) : "l"(v));
}
__device__ __forceinline__ ull fma2(ull a, ull b, ull c) {
    ull d; asm("fma.rn.f32x2 %0, %1, %2, %3;" : "=l"(d) : "l"(a), "l"(b), "l"(c)); return d;
}

// ---------------- scratch ----------------
__device__ float g_xcat[(size_t)BATCH * 1024 * HP];
__device__ float g_x2[(size_t)BATCH * 1024 * HP];
__device__ float g_cls1T[(size_t)BATCH * HP * NOUT];
__device__ float g_c1a[(size_t)BATCH * 48 * HR * HR];

// =====================================================================
// conv3x3 on 16x16, SAME, BN+ReLU.  Block: 256 thr = 4 cin-quarters x
// 64 spatial threads (each owns a 2x2 output patch). Block computes 16 oc.
// Inner math: f32x2 packed over horizontal position pairs; weights stored
// duplicated in shared so one LDS.64 = packed broadcast operand.
// =====================================================================
template<int CIN>
__global__ __launch_bounds__(256) void conv3x3_v2(
    const float* __restrict__ in, const float* __restrict__ w,
    const float* __restrict__ scale, const float* __restrict__ shift,
    float* __restrict__ out, int out_cstride)
{
    constexpr int CINQ = CIN / 4;
    const int b = blockIdx.y, ocg = blockIdx.x, tid = threadIdx.x;
    const int q = tid >> 6, s = tid & 63;
    const int py0 = (s >> 3) << 1, px0 = (s & 7) << 1;

    __shared__ __align__(16) char smem[19584];
    float* sIn = (float*)smem;            // [4 quarters][2 cin][324]
    ull*   sW  = (ull*)(smem + 10368);    // [4 quarters][2 cin][144]

    ull accA[16], accB[16];
#pragma unroll
    for (int i = 0; i < 16; i++) { accA[i] = 0ull; accB[i] = 0ull; }

    const float* ip0 = in + ((size_t)b * CIN + q * CINQ) * 256;
    const int ocbase = ocg * 16;

    for (int c0 = 0; c0 < CINQ; c0 += 2) {
        // load 2 input planes for this quarter's cin
        for (int i = s; i < 648; i += 64) {
            int cc = (i >= 324) ? 1 : 0, j = i - cc * 324;
            int r = j / 18, c = j - r * 18;
            int y = r - 1, x = c - 1;
            float v = 0.f;
            if ((unsigned)y < 16u && (unsigned)x < 16u)
                v = ip0[((size_t)(c0 + cc) << 8) + (y << 4) + x];
            sIn[q * 648 + i] = v;
        }
        // load + duplicate weights
        for (int i = s; i < 288; i += 64) {
            int cc = (i >= 144) ? 1 : 0, j = i - cc * 144;
            int oc = j / 9, k = j - oc * 9;
            float wv = w[((size_t)(ocbase + oc) * CIN + q * CINQ + c0 + cc) * 9 + k];
            sW[q * 288 + i] = pack2(wv, wv);
        }
        __syncthreads();
#pragma unroll
        for (int cc = 0; cc < 2; cc++) {
            const float* P = sIn + q * 648 + cc * 324;
            float xv[4][4];
#pragma unroll
            for (int r = 0; r < 4; r++)
#pragma unroll
                for (int c = 0; c < 4; c++)
                    xv[r][c] = P[(py0 + r) * 18 + px0 + c];
            ull pr[4][3];
#pragma unroll
            for (int r = 0; r < 4; r++)
#pragma unroll
                for (int j = 0; j < 3; j++)
                    pr[r][j] = pack2(xv[r][j], xv[r][j + 1]);
            const ull* W = sW + q * 288 + cc * 144;
#pragma unroll
            for (int oc = 0; oc < 16; oc++) {
#pragma unroll
                for (int ky = 0; ky < 3; ky++)
#pragma unroll
                    for (int kx = 0; kx < 3; kx++) {
                        ull w64 = W[oc * 9 + ky * 3 + kx];
                        accA[oc] = fma2(pr[ky][kx], w64, accA[oc]);
                        accB[oc] = fma2(pr[ky + 1][kx], w64, accB[oc]);
                    }
            }
        }
        __syncthreads();
    }

    // reduce 4 cin-quarters through shared
    float* sRed = (float*)smem;   // [16 oc][256 pos]
    for (int qq = 0; qq < 4; qq++) {
        if (q == qq) {
#pragma unroll
            for (int oc = 0; oc < 16; oc++) {
                float a0, a1, b0, b1;
                unpack2(accA[oc], a0, a1);
                unpack2(accB[oc], b0, b1);
                int p = py0 * 16 + px0;
                if (qq == 0) {
                    sRed[oc * 256 + p] = a0;       sRed[oc * 256 + p + 1] = a1;
                    sRed[oc * 256 + p + 16] = b0;  sRed[oc * 256 + p + 17] = b1;
                } else {
                    sRed[oc * 256 + p] += a0;      sRed[oc * 256 + p + 1] += a1;
                    sRed[oc * 256 + p + 16] += b0; sRed[oc * 256 + p + 17] += b1;
                }
            }
        }
        __syncthreads();
    }
    for (int i = tid; i < 4096; i += 256) {
        int oc = i >> 8, pos = i & 255;
        int gc = ocbase + oc;
        float r = fmaf(sRed[i], scale[gc], shift[gc]);
        out[((size_t)b * out_cstride + gc) * 256 + pos] = fmaxf(r, 0.f);
    }
}

// ---------------- global pooling broadcast ----------------
__global__ __launch_bounds__(256) void gp_kernel()
{
    const int c = blockIdx.x, b = blockIdx.y, tid = threadIdx.x;
    size_t base = ((size_t)b * 1024 + c) * 256;
    float v = g_xcat[base + tid];
#pragma unroll
    for (int o = 16; o; o >>= 1) v += __shfl_xor_sync(0xffffffffu, v, o);
    __shared__ float red[8];
    __shared__ float meanv;
    if ((tid & 31) == 0) red[tid >> 5] = v;
    __syncthreads();
    if (tid == 0) {
        float t = 0.f;
#pragma unroll
        for (int i = 0; i < 8; i++) t += red[i];
        meanv = t * (1.f / 256.f);
    }
    __syncthreads();
    g_xcat[base + (size_t)512 * 256 + tid] = meanv;
}

// =====================================================================
// cls1: 1x1 conv 1024 -> 4928 as packed GEMM, writes [b][pos][ch].
// Block 256 thr = 8 oc-groups x 32 pos-threads. Each thread: 4 position
// pairs (8 consecutive pos, natural LDS.64) x 8 oc.  Block oc = 64.
// =====================================================================
__global__ __launch_bounds__(256) void cls1_v2(
    const float* __restrict__ x2, const float* __restrict__ w,
    const float* __restrict__ bias, float* __restrict__ outT)
{
    const int b = blockIdx.y, ocb = blockIdx.x * 64, tid = threadIdx.x;
    const int og = tid >> 5, sp = tid & 31;

    __shared__ __align__(16) char smem[24576];
    float* sX = (float*)smem;            // [16 cin][256 pos]
    ull*   sW = (ull*)(smem + 16384);    // [16 cin][64 oc] duplicated

    ull acc[8][4];
#pragma unroll
    for (int i = 0; i < 8; i++)
#pragma unroll
        for (int j = 0; j < 4; j++) acc[i][j] = 0ull;

    for (int c0 = 0; c0 < 1024; c0 += 16) {
        for (int i = tid; i < 4096; i += 256) {
            int cc = i >> 8, p = i & 255;
            sX[i] = x2[(((size_t)b << 10) + (c0 + cc)) * 256 + p];
        }
        for (int i = tid; i < 1024; i += 256) {
            int cc = i >> 6, oc = i & 63;
            float wv = w[(size_t)(ocb + oc) * 1024 + c0 + cc];
            sW[i] = pack2(wv, wv);
        }
        __syncthreads();
#pragma unroll
        for (int cc = 0; cc < 16; cc++) {
            const ull* xr = (const ull*)(sX + cc * 256) + sp * 4;
            ull xp[4];
#pragma unroll
            for (int j = 0; j < 4; j++) xp[j] = xr[j];
#pragma unroll
            for (int oc = 0; oc < 8; oc++) {
                ull w64 = sW[cc * 64 + og * 8 + oc];
#pragma unroll
                for (int j = 0; j < 4; j++) acc[oc][j] = fma2(xp[j], w64, acc[oc][j]);
            }
        }
        __syncthreads();
    }
#pragma unroll
    for (int oc = 0; oc < 8; oc++) {
        int gc = ocb + og * 8 + oc;
        float bv = bias[gc];
#pragma unroll
        for (int j = 0; j < 4; j++) {
            float a0, a1;
            unpack2(acc[oc][j], a0, a1);
            int pos = sp * 8 + 2 * j;
            float* o = outT + ((size_t)(b * 256 + pos)) * NOUT + gc;
            o[0] = a0 + bv;
            o[NOUT] = a1 + bv;
        }
    }
}

// =====================================================================
// c1a: conv3x3 256->48 on 128x128, SAME, BN+ReLU.
// Block 256 thr = 4 oc-groups (12 oc each) x 64 spatial threads (2x2
// patch in a 16x16 tile). All groups share the input plane.
// =====================================================================
__global__ __launch_bounds__(256) void c1a_v2(
    const float* __restrict__ in, const float* __restrict__ w,
    const float* __restrict__ scale, const float* __restrict__ shift,
    float* __restrict__ out)
{
    const int b = blockIdx.y, tile = blockIdx.x, tid = threadIdx.x;
    const int ty0 = (tile >> 3) << 4, tx0 = (tile & 7) << 4;
    const int og = tid >> 6, s = tid & 63;
    const int py0 = (s >> 3) << 1, px0 = (s & 7) << 1;

    __shared__ __align__(16) char smem[9504];
    float* sIn = (float*)smem;            // [2 cin][324]
    ull*   sW  = (ull*)(smem + 2592);     // [2 cin][48*9] duplicated

    ull accA[12], accB[12];
#pragma unroll
    for (int i = 0; i < 12; i++) { accA[i] = 0ull; accB[i] = 0ull; }

    for (int c0 = 0; c0 < 256; c0 += 2) {
        for (int i = tid; i < 648; i += 256) {
            int cc = (i >= 324) ? 1 : 0, j = i - cc * 324;
            int r = j / 18, c = j - r * 18;
            int y = ty0 - 1 + r, x = tx0 - 1 + c;
            float v = 0.f;
            if ((unsigned)y < 128u && (unsigned)x < 128u)
                v = in[(((size_t)b * 256 + c0 + cc) << 14) + (y << 7) + x];
            sIn[i] = v;
        }
        for (int i = tid; i < 864; i += 256) {
            int cc = (i >= 432) ? 1 : 0, j = i - cc * 432;
            int oc = j / 9, k = j - oc * 9;
            float wv = w[((size_t)oc * 256 + c0 + cc) * 9 + k];
            sW[i] = pack2(wv, wv);
        }
        __syncthreads();
#pragma unroll
        for (int cc = 0; cc < 2; cc++) {
            const float* P = sIn + cc * 324;
            float xv[4][4];
#pragma unroll
            for (int r = 0; r < 4; r++)
#pragma unroll
                for (int c = 0; c < 4; c++)
                    xv[r][c] = P[(py0 + r) * 18 + px0 + c];
            ull pr[4][3];
#pragma unroll
            for (int r = 0; r < 4; r++)
#pragma unroll
                for (int j = 0; j < 3; j++)
                    pr[r][j] = pack2(xv[r][j], xv[r][j + 1]);
            const ull* W = sW + cc * 432 + og * 108;
#pragma unroll
            for (int oc = 0; oc < 12; oc++) {
#pragma unroll
                for (int ky = 0; ky < 3; ky++)
#pragma unroll
                    for (int kx = 0; kx < 3; kx++) {
                        ull w64 = W[oc * 9 + ky * 3 + kx];
                        accA[oc] = fma2(pr[ky][kx], w64, accA[oc]);
                        accB[oc] = fma2(pr[ky + 1][kx], w64, accB[oc]);
                    }
            }
        }
        __syncthreads();
    }
#pragma unroll
    for (int oc = 0; oc < 12; oc++) {
        int gc = og * 12 + oc;
        float sc = scale[gc], sh = shift[gc];
        float a0, a1, b0, b1;
        unpack2(accA[oc], a0, a1);
        unpack2(accB[oc], b0, b1);
        int y = ty0 + py0, x = tx0 + px0;
        float* ob = out + (((size_t)b * 48 + gc) << 14) + (y << 7) + x;
        ob[0]   = fmaxf(fmaf(a0, sc, sh), 0.f);
        ob[1]   = fmaxf(fmaf(a1, sc, sh), 0.f);
        ob[128] = fmaxf(fmaf(b0, sc, sh), 0.f);
        ob[129] = fmaxf(fmaf(b1, sc, sh), 0.f);
    }
}

// ---------------- fused: c1b + coord + cat-BN + dynamic MLP ----------------
__global__ __launch_bounds__(256) void fused_final(
    const float* __restrict__ cls1T, const float* __restrict__ c1a,
    const float* __restrict__ c1b_w, const float* __restrict__ c1b_b,
    const float* __restrict__ cat_scale, const float* __restrict__ cat_shift,
    float* __restrict__ out)
{
    const int b = blockIdx.y, lpos = blockIdx.x;
    const int ly = lpos >> 4, lx = lpos & 15;
    const int tid = threadIdx.x;
    const int px = tid & 63, q = tid >> 6;
    const int py = px >> 3, pxx = px & 7;

    __shared__ float sP[NOUT];
    __shared__ float sA[48 * 64];
    __shared__ float sI[18 * 64];
    __shared__ float sH0[16 * 64];
    __shared__ float sH1[16 * 64];
    __shared__ float sWb[768 + 16];

    const float* pp = cls1T + (size_t)(b * 256 + lpos) * NOUT;
    for (int i = tid; i < NOUT; i += 256) sP[i] = pp[i];
    for (int i = tid; i < 48 * 64; i += 256) {
        int ch = i >> 6, p = i & 63;
        sA[i] = c1a[(((size_t)b * 48 + ch) << 14) + ((ly * 8 + (p >> 3)) << 7) + lx * 8 + (p & 7)];
    }
    for (int i = tid; i < 768; i += 256) sWb[i] = c1b_w[i];
    if (tid < 16) sWb[768 + tid] = c1b_b[tid];
    __syncthreads();

#pragma unroll
    for (int jj = 0; jj < 4; jj++) {
        int j = q * 4 + jj;
        float s = sWb[768 + j];
#pragma unroll
        for (int c = 0; c < 48; c++)
            s = fmaf(sA[c * 64 + px], sWb[j * 48 + c], s);
        sI[(2 + j) * 64 + px] = fmaf(s, cat_scale[2 + j], cat_shift[2 + j]);
    }
    if (q == 0) {
        sI[px]      = fmaf((float)pxx * 0.125f, cat_scale[0], cat_shift[0]);
        sI[64 + px] = fmaf((float)py  * 0.125f, cat_scale[1], cat_shift[1]);
    }
    __syncthreads();

#pragma unroll
    for (int jj = 0; jj < 4; jj++) {
        int o = q * 4 + jj;
        float s = sP[288 + o];
#pragma unroll
        for (int c = 0; c < 18; c++)
            s = fmaf(sP[o * 18 + c], sI[c * 64 + px], s);
        sH0[o * 64 + px] = fmaxf(s, 0.f);
    }
    __syncthreads();

#pragma unroll
    for (int jj = 0; jj < 4; jj++) {
        int o = q * 4 + jj;
        float s = sP[560 + o];
#pragma unroll
        for (int c = 0; c < 16; c++)
            s = fmaf(sP[304 + o * 16 + c], sH0[c * 64 + px], s);
        sH1[o * 64 + px] = fmaxf(s, 0.f);
    }
    __syncthreads();

    float hr[16];
#pragma unroll
    for (int c = 0; c < 16; c++) hr[c] = sH1[c * 64 + px];
    const int y = ly * 8 + py, x = lx * 8 + pxx;
    float* ob = out + (((size_t)b * 256) << 14) + (y << 7) + x;
#pragma unroll 4
    for (int oo = 0; oo < 64; oo++) {
        int o = q * 64 + oo;
        float s = sP[4672 + o];
#pragma unroll
        for (int c = 0; c < 16; c++)
            s = fmaf(sP[576 + o * 16 + c], hr[c], s);
        ob[(size_t)o << 14] = s;
    }
}

// ---------------- host launcher ----------------
extern "C" void kernel_launch(void* const* d_in, const int* in_sizes, int n_in,
                              void* d_out, int out_size)
{
    const float* res5 = (const float*)d_in[0];
    const float* res2 = (const float*)d_in[1];
    const float* bw   = (const float*)d_in[2];
    const float* bn1s = (const float*)d_in[3];
    const float* bn1h = (const float*)d_in[4];
    const float* c0w  = (const float*)d_in[5];
    const float* bn2s = (const float*)d_in[6];
    const float* bn2h = (const float*)d_in[7];
    const float* c1w  = (const float*)d_in[8];
    const float* c1b  = (const float*)d_in[9];
    const float* aw   = (const float*)d_in[10];
    const float* bn3s = (const float*)d_in[11];
    const float* bn3h = (const float*)d_in[12];
    const float* bw2  = (const float*)d_in[13];
    const float* bb2  = (const float*)d_in[14];
    const float* cats = (const float*)d_in[15];
    const float* cath = (const float*)d_in[16];
    float* out = (float*)d_out;

    float *xcat, *x2, *cls1T, *c1a;
    cudaGetSymbolAddress((void**)&xcat,  g_xcat);
    cudaGetSymbolAddress((void**)&x2,    g_x2);
    cudaGetSymbolAddress((void**)&cls1T, g_cls1T);
    cudaGetSymbolAddress((void**)&c1a,   g_c1a);

    conv3x3_v2<2048><<<dim3(32, BATCH), 256>>>(res5, bw, bn1s, bn1h, xcat, 1024);
    gp_kernel<<<dim3(512, BATCH), 256>>>();
    conv3x3_v2<1024><<<dim3(64, BATCH), 256>>>(xcat, c0w, bn2s, bn2h, x2, 1024);
    cls1_v2<<<dim3(77, BATCH), 256>>>(x2, c1w, c1b, cls1T);
    c1a_v2<<<dim3(64, BATCH), 256>>>(res2, aw, bn3s, bn3h, c1a);
    fused_final<<<dim3(256, BATCH), 256>>>(cls1T, c1a, bw2, bb2, cats, cath, out);
}

// round 6
// speedup vs baseline: 2.9148x; 2.9148x over previous
#include <cuda_runtime.h>
#include <cuda_bf16.h>
#include <cstdint>

typedef __nv_bfloat16 bf16;
#define NOUT 4928

// ---------------- scratch (device globals; sizes in elements) ----------------
__device__ __align__(16) bf16 g_Xs5[(size_t)2048 * 6144];     // res5 aug [pos][3*2048]
__device__ __align__(16) bf16 g_W1 [(size_t)512 * 55296];     // conv1 W aug [oc][9*3*2048]
__device__ __align__(16) bf16 g_X1 [(size_t)2048 * 3072];     // x1 aug [pos][3*1024]
__device__ __align__(16) bf16 g_W2 [(size_t)1024 * 27648];    // conv2 W aug
__device__ __align__(16) bf16 g_X2 [(size_t)2048 * 3072];     // x2 aug
__device__ __align__(16) bf16 g_W3 [(size_t)4992 * 3072];     // cls1 W aug (oc padded)
__device__ __align__(16) bf16 g_Xr2[(size_t)131072 * 768];    // res2 aug [pos][3*256]
__device__ __align__(16) bf16 g_W4 [(size_t)64 * 6912];       // c1a W aug (oc padded)
__device__ float g_cls1T[(size_t)2048 * NOUT];                // hyper params [pos][4928]
__device__ float g_c1aT [(size_t)131072 * 48];                // c1a out [pos][48]

// ---------------- helpers ----------------
__device__ __forceinline__ void split2(float v, bf16& h, bf16& l) {
    h = __float2bfloat16(v);
    l = __float2bfloat16(v - __bfloat162float(h));
}
__device__ __forceinline__ unsigned pkb(bf16 a, bf16 b) {
    return (unsigned)__bfloat16_as_ushort(a) | ((unsigned)__bfloat16_as_ushort(b) << 16);
}
__device__ __forceinline__ unsigned s2u(const void* p) {
    return (unsigned)__cvta_generic_to_shared(p);
}
__device__ __forceinline__ void cpa16(unsigned d, const void* s, unsigned sz) {
    asm volatile("cp.async.ca.shared.global [%0], [%1], 16, %2;" :: "r"(d), "l"(s), "r"(sz));
}
__device__ __forceinline__ void cpa_commit() {
    asm volatile("cp.async.commit_group;" ::: "memory");
}
template<int N> __device__ __forceinline__ void cpa_wait() {
    asm volatile("cp.async.wait_group %0;" :: "n"(N) : "memory");
}
__device__ __forceinline__ void ldm4(unsigned* r, unsigned a) {
    asm volatile("ldmatrix.sync.aligned.m8n8.x4.shared.b16 {%0,%1,%2,%3}, [%4];"
        : "=r"(r[0]), "=r"(r[1]), "=r"(r[2]), "=r"(r[3]) : "r"(a));
}
__device__ __forceinline__ void mma16816(float* d, const unsigned* a, const unsigned* b) {
    asm volatile("mma.sync.aligned.m16n8k16.row.col.f32.bf16.bf16.f32 "
        "{%0,%1,%2,%3}, {%4,%5,%6,%7}, {%8,%9}, {%0,%1,%2,%3};"
        : "+f"(d[0]), "+f"(d[1]), "+f"(d[2]), "+f"(d[3])
        : "r"(a[0]), "r"(a[1]), "r"(a[2]), "r"(a[3]), "r"(b[0]), "r"(b[1]));
}

// =====================================================================
// HMMA GEMM: D[row, col] = sum_k A'[row,k] * B'[col,k]  (bf16 in, fp32 acc)
// A' rows are positions (implicit im2col when CONV3); B' rows are oc.
// Block tile 128x64, warp tile 32x32, BK=32, double-buffered cp.async.
// SMEM rows padded to 80B => conflict-free ldmatrix (no swizzle needed).
// =====================================================================
template<bool CONV3>
__global__ __launch_bounds__(256) void gemm_mma(
    const bf16* __restrict__ A, const bf16* __restrict__ B,
    int C3, int imh, int imw, int nk, int Kb,
    int epi, int nvalid,
    const float* __restrict__ scale, const float* __restrict__ shift,
    const float* __restrict__ bias,
    bf16* __restrict__ Oaug, int outc,
    float* __restrict__ Of, int ofc)
{
    __shared__ __align__(16) char sm[2 * (128 * 80 + 64 * 80)];  // 30720 B
    const int tid = threadIdx.x;
    const int nb = blockIdx.x, mtile = blockIdx.y;
    const int warp = tid >> 5, lane = tid & 31;
    const int m0 = (warp >> 1) * 32, n0 = (warp & 1) * 32;
    const unsigned sbase = s2u(sm);
    const int imgpix = imh * imw;

    // A-loader per-thread geometry (2 x uint4 per thread)
    int arow[2], ay[2], ax[2], apb[2];
#pragma unroll
    for (int j = 0; j < 2; j++) {
        int item = tid + 256 * j;
        arow[j] = item >> 2;
        int g = mtile * 128 + arow[j];
        if (CONV3) {
            int bb = g / imgpix, lp = g - bb * imgpix;
            ay[j] = lp / imw; ax[j] = lp - ay[j] * imw; apb[j] = bb * imgpix;
        } else { ay[j] = 0; ax[j] = 0; apb[j] = g; }
    }
    const int ac = tid & 3;
    const int brow = tid >> 2, bc = tid & 3;

    auto load_chunk = [&](int kc, int st) {
        unsigned Ab = sbase + st * 15360;
        unsigned Bb = Ab + 10240;
        int k0 = kc * 32;
        int dy = 0, dx = 0, cb = k0;
        if (CONV3) {
            int rk = k0 / C3; cb = k0 - rk * C3;
            int r3 = rk / 3; dy = r3 - 1; dx = rk - r3 * 3 - 1;
        }
#pragma unroll
        for (int j = 0; j < 2; j++) {
            const bf16* src;
            unsigned sz = 16;
            if (CONV3) {
                int y2 = ay[j] + dy, x2 = ax[j] + dx;
                bool v = ((unsigned)y2 < (unsigned)imh) && ((unsigned)x2 < (unsigned)imw);
                src = A + (size_t)(apb[j] + y2 * imw + x2) * C3 + cb + ac * 8;
                if (!v) { src = A; sz = 0; }
            } else {
                src = A + (size_t)apb[j] * C3 + k0 + ac * 8;
            }
            cpa16(Ab + arow[j] * 80 + ac * 16, src, sz);
        }
        cpa16(Bb + brow * 80 + bc * 16,
              B + (size_t)(nb * 64 + brow) * Kb + k0 + bc * 8, 16);
    };

    float acc[2][4][4];
#pragma unroll
    for (int a = 0; a < 2; a++)
#pragma unroll
        for (int b2 = 0; b2 < 4; b2++)
#pragma unroll
            for (int c = 0; c < 4; c++) acc[a][b2][c] = 0.f;

    auto compute = [&](int st) {
        unsigned Ab = sbase + st * 15360;
        unsigned Bb = Ab + 10240;
#pragma unroll
        for (int step = 0; step < 2; step++) {
            unsigned af[2][4], bfr[2][4];
            {
                int r = m0 + (lane & 15);
                int ch = step * 2 + (lane >> 4);
                ldm4(af[0], Ab + r * 80 + ch * 16);
                ldm4(af[1], Ab + (r + 16) * 80 + ch * 16);
            }
            {
                int r = n0 + (lane & 7) + ((lane >> 4) << 3);
                int ch = step * 2 + ((lane >> 3) & 1);
                ldm4(bfr[0], Bb + r * 80 + ch * 16);
                ldm4(bfr[1], Bb + (r + 16) * 80 + ch * 16);
            }
#pragma unroll
            for (int mt = 0; mt < 2; mt++)
#pragma unroll
                for (int nt = 0; nt < 4; nt++)
                    mma16816(acc[mt][nt], af[mt], &bfr[nt >> 1][(nt & 1) * 2]);
        }
    };

    load_chunk(0, 0);
    cpa_commit();
    for (int kc = 0; kc < nk; kc++) {
        int cur = kc & 1;
        if (kc + 1 < nk) {
            load_chunk(kc + 1, cur ^ 1);
            cpa_commit();
            cpa_wait<1>();
        } else {
            cpa_wait<0>();
        }
        __syncthreads();
        compute(cur);
        __syncthreads();
    }

    // ---- epilogue ----
#pragma unroll
    for (int mt = 0; mt < 2; mt++)
#pragma unroll
        for (int nt = 0; nt < 4; nt++) {
            float* d = acc[mt][nt];
            int row = mtile * 128 + m0 + mt * 16 + (lane >> 2);
            int col = nb * 64 + n0 + nt * 8 + (lane & 3) * 2;
#pragma unroll
            for (int h = 0; h < 2; h++) {
                int r = row + h * 8;
                float v0 = d[h * 2 + 0], v1 = d[h * 2 + 1];
                if (epi == 0) {
                    v0 = fmaxf(fmaf(v0, scale[col], shift[col]), 0.f);
                    v1 = fmaxf(fmaf(v1, scale[col + 1], shift[col + 1]), 0.f);
                    bf16 h0, l0, h1, l1; split2(v0, h0, l0); split2(v1, h1, l1);
                    size_t base = (size_t)r * 3 * outc + col;
                    *(unsigned*)(Oaug + base) = pkb(h0, h1);
                    *(unsigned*)(Oaug + base + outc) = pkb(l0, l1);
                    *(unsigned*)(Oaug + base + 2 * outc) = pkb(h0, h1);
                } else if (epi == 1) {
                    if (col < nvalid) {
                        float2 o = make_float2(v0 + bias[col], v1 + bias[col + 1]);
                        *(float2*)(Of + (size_t)r * ofc + col) = o;
                    }
                } else {
                    if (col < nvalid) {
                        float2 o;
                        o.x = fmaxf(fmaf(v0, scale[col], shift[col]), 0.f);
                        o.y = fmaxf(fmaf(v1, scale[col + 1], shift[col + 1]), 0.f);
                        *(float2*)(Of + (size_t)r * ofc + col) = o;
                    }
                }
            }
        }
}

// ---------------- prep: NCHW fp32 -> [pos][3C] augmented bf16 ----------------
__global__ __launch_bounds__(256) void split_aug(
    const float* __restrict__ in, bf16* __restrict__ out, int C, int HW)
{
    __shared__ float t[32][33];
    const int b = blockIdx.z, c0 = blockIdx.y * 32, p0 = blockIdx.x * 32;
    const int tx = threadIdx.x & 31, ty = threadIdx.x >> 5;
#pragma unroll
    for (int r = 0; r < 4; r++)
        t[ty + 8 * r][tx] = in[((size_t)b * C + c0 + ty + 8 * r) * HW + p0 + tx];
    __syncthreads();
#pragma unroll
    for (int r = 0; r < 4; r++) {
        int p = p0 + ty + 8 * r;
        float v = t[tx][ty + 8 * r];
        bf16 h, l; split2(v, h, l);
        size_t o = ((size_t)b * HW + p) * 3 * C + c0 + tx;
        out[o] = h; out[o + C] = l; out[o + 2 * C] = h;
    }
}

// ---------------- prep: conv weight OIHW -> [oc][tap][3C] augmented ----------------
__global__ __launch_bounds__(256) void wsplit_conv_aug(
    const float* __restrict__ w, bf16* __restrict__ out, int C, int OC)
{
    int idx = blockIdx.x * 256 + threadIdx.x;  // over OCP*9*C
    int oc = idx / (9 * C); int rem = idx - oc * 9 * C;
    int tap = rem / C; int c = rem - tap * C;
    float v = (oc < OC) ? w[((size_t)oc * C + c) * 9 + tap] : 0.f;
    bf16 h, l; split2(v, h, l);
    size_t base = (size_t)oc * (27 * C) + (size_t)tap * 3 * C;
    out[base + c] = h; out[base + C + c] = h; out[base + 2 * C + c] = l;
}

// ---------------- prep: cls1 weight [4928][1024] -> [4992][3072] augmented ----------------
__global__ __launch_bounds__(256) void wsplit_dense_aug(
    const float* __restrict__ w, bf16* __restrict__ out)
{
    int idx = blockIdx.x * 256 + threadIdx.x;  // 4992*1024
    int oc = idx >> 10, c = idx & 1023;
    float v = (oc < NOUT) ? w[(size_t)oc * 1024 + c] : 0.f;
    bf16 h, l; split2(v, h, l);
    size_t base = (size_t)oc * 3072;
    out[base + c] = h; out[base + 1024 + c] = h; out[base + 2048 + c] = l;
}

// ---------------- global pool: mean of ch 0..511 -> aug ch 512..1023 ----------------
__global__ __launch_bounds__(512) void gp2(bf16* __restrict__ X)
{
    const int b = blockIdx.x, c = threadIdx.x;   // c in [0,512)
    float s = 0.f;
    for (int p = 0; p < 256; p++) {
        size_t i = ((size_t)(b * 256 + p)) * 3072 + c;
        s += __bfloat162float(X[i]) + __bfloat162float(X[i + 1024]);
    }
    float m = s * (1.f / 256.f);
    bf16 h, l; split2(m, h, l);
    for (int p = 0; p < 256; p++) {
        size_t base = ((size_t)(b * 256 + p)) * 3072 + 512 + c;
        X[base] = h; X[base + 1024] = l; X[base + 2048] = h;
    }
}

// ---------------- fused: c1b + coord + cat-BN + 3-layer dynamic MLP ----------------
__global__ __launch_bounds__(256) void fused_final(
    const float* __restrict__ cls1T, const float* __restrict__ c1aT,
    const float* __restrict__ c1b_w, const float* __restrict__ c1b_b,
    const float* __restrict__ cat_scale, const float* __restrict__ cat_shift,
    float* __restrict__ out)
{
    const int b = blockIdx.y, lpos = blockIdx.x;
    const int ly = lpos >> 4, lx = lpos & 15;
    const int tid = threadIdx.x;
    const int px = tid & 63, q = tid >> 6;
    const int py = px >> 3, pxx = px & 7;

    __shared__ float sP[NOUT];
    __shared__ float sA[48 * 64];
    __shared__ float sI[18 * 64];
    __shared__ float sH0[16 * 64];
    __shared__ float sH1[16 * 64];
    __shared__ float sWb[768 + 16];

    const float* pp = cls1T + (size_t)(b * 256 + lpos) * NOUT;
    for (int i = tid; i < NOUT; i += 256) sP[i] = pp[i];
    for (int i = tid; i < 48 * 64; i += 256) {
        int p = i / 48, ch = i - p * 48;
        int yy = ly * 8 + (p >> 3), xx = lx * 8 + (p & 7);
        sA[ch * 64 + p] = c1aT[((size_t)b * 16384 + yy * 128 + xx) * 48 + ch];
    }
    for (int i = tid; i < 768; i += 256) sWb[i] = c1b_w[i];
    if (tid < 16) sWb[768 + tid] = c1b_b[tid];
    __syncthreads();

#pragma unroll
    for (int jj = 0; jj < 4; jj++) {
        int j = q * 4 + jj;
        float s = sWb[768 + j];
#pragma unroll
        for (int c = 0; c < 48; c++)
            s = fmaf(sA[c * 64 + px], sWb[j * 48 + c], s);
        sI[(2 + j) * 64 + px] = fmaf(s, cat_scale[2 + j], cat_shift[2 + j]);
    }
    if (q == 0) {
        sI[px]      = fmaf((float)pxx * 0.125f, cat_scale[0], cat_shift[0]);
        sI[64 + px] = fmaf((float)py  * 0.125f, cat_scale[1], cat_shift[1]);
    }
    __syncthreads();

#pragma unroll
    for (int jj = 0; jj < 4; jj++) {
        int o = q * 4 + jj;
        float s = sP[288 + o];
#pragma unroll
        for (int c = 0; c < 18; c++)
            s = fmaf(sP[o * 18 + c], sI[c * 64 + px], s);
        sH0[o * 64 + px] = fmaxf(s, 0.f);
    }
    __syncthreads();

#pragma unroll
    for (int jj = 0; jj < 4; jj++) {
        int o = q * 4 + jj;
        float s = sP[560 + o];
#pragma unroll
        for (int c = 0; c < 16; c++)
            s = fmaf(sP[304 + o * 16 + c], sH0[c * 64 + px], s);
        sH1[o * 64 + px] = fmaxf(s, 0.f);
    }
    __syncthreads();

    float hr[16];
#pragma unroll
    for (int c = 0; c < 16; c++) hr[c] = sH1[c * 64 + px];
    const int y = ly * 8 + py, x = lx * 8 + pxx;
    float* ob = out + (((size_t)b * 256) << 14) + (y << 7) + x;
#pragma unroll 4
    for (int oo = 0; oo < 64; oo++) {
        int o = q * 64 + oo;
        float s = sP[4672 + o];
#pragma unroll
        for (int c = 0; c < 16; c++)
            s = fmaf(sP[576 + o * 16 + c], hr[c], s);
        ob[(size_t)o << 14] = s;
    }
}

// ---------------- host launcher ----------------
extern "C" void kernel_launch(void* const* d_in, const int* in_sizes, int n_in,
                              void* d_out, int out_size)
{
    const float* res5 = (const float*)d_in[0];
    const float* res2 = (const float*)d_in[1];
    const float* bw   = (const float*)d_in[2];
    const float* bn1s = (const float*)d_in[3];
    const float* bn1h = (const float*)d_in[4];
    const float* c0w  = (const float*)d_in[5];
    const float* bn2s = (const float*)d_in[6];
    const float* bn2h = (const float*)d_in[7];
    const float* c1w  = (const float*)d_in[8];
    const float* c1b  = (const float*)d_in[9];
    const float* aw   = (const float*)d_in[10];
    const float* bn3s = (const float*)d_in[11];
    const float* bn3h = (const float*)d_in[12];
    const float* bw2  = (const float*)d_in[13];
    const float* bb2  = (const float*)d_in[14];
    const float* cats = (const float*)d_in[15];
    const float* cath = (const float*)d_in[16];
    float* out = (float*)d_out;

    bf16 *Xs5, *W1, *X1, *W2, *X2, *W3, *Xr2, *W4;
    float *cls1T, *c1aT;
    cudaGetSymbolAddress((void**)&Xs5, g_Xs5);
    cudaGetSymbolAddress((void**)&W1,  g_W1);
    cudaGetSymbolAddress((void**)&X1,  g_X1);
    cudaGetSymbolAddress((void**)&W2,  g_W2);
    cudaGetSymbolAddress((void**)&X2,  g_X2);
    cudaGetSymbolAddress((void**)&W3,  g_W3);
    cudaGetSymbolAddress((void**)&Xr2, g_Xr2);
    cudaGetSymbolAddress((void**)&W4,  g_W4);
    cudaGetSymbolAddress((void**)&cls1T, g_cls1T);
    cudaGetSymbolAddress((void**)&c1aT,  g_c1aT);

    // ---- prep: augmented split operands ----
    split_aug<<<dim3(8, 64, 8), 256>>>(res5, Xs5, 2048, 256);
    split_aug<<<dim3(512, 8, 8), 256>>>(res2, Xr2, 256, 16384);
    wsplit_conv_aug<<<(512 * 9 * 2048) / 256, 256>>>(bw, W1, 2048, 512);
    wsplit_conv_aug<<<(1024 * 9 * 1024) / 256, 256>>>(c0w, W2, 1024, 1024);
    wsplit_conv_aug<<<(64 * 9 * 256) / 256, 256>>>(aw, W4, 256, 48);
    wsplit_dense_aug<<<(4992 * 1024) / 256, 256>>>(c1w, W3);

    // ---- conv1: im2col GEMM [2048 x 55296] * [512 x 55296] -> X1 aug ch 0..511 ----
    gemm_mma<true><<<dim3(8, 16), 256>>>(
        Xs5, W1, 6144, 16, 16, 1728, 55296, 0, 512,
        bn1s, bn1h, nullptr, X1, 1024, nullptr, 0);
    // ---- global pool broadcast into aug ch 512..1023 ----
    gp2<<<8, 512>>>(X1);
    // ---- conv2: [2048 x 27648] * [1024 x 27648] -> X2 aug ----
    gemm_mma<true><<<dim3(16, 16), 256>>>(
        X1, W2, 3072, 16, 16, 864, 27648, 0, 1024,
        bn2s, bn2h, nullptr, X2, 1024, nullptr, 0);
    // ---- cls1: [2048 x 3072] * [4992 x 3072] -> cls1T fp32 ----
    gemm_mma<false><<<dim3(78, 16), 256>>>(
        X2, W3, 3072, 16, 16, 96, 3072, 1, NOUT,
        nullptr, nullptr, c1b, nullptr, 0, cls1T, NOUT);
    // ---- c1a: [131072 x 6912] * [64 x 6912] -> c1aT fp32 ----
    gemm_mma<true><<<dim3(1, 1024), 256>>>(
        Xr2, W4, 768, 128, 128, 216, 6912, 2, 48,
        bn3s, bn3h, nullptr, nullptr, 0, c1aT, 48);
    // ---- fused tail ----
    fused_final<<<dim3(256, 8), 256>>>(cls1T, c1aT, bw2, bb2, cats, cath, out);
}

// round 7
// speedup vs baseline: 3.2410x; 1.1119x over previous
#include <cuda_runtime.h>
#include <cuda_bf16.h>
#include <cstdint>

typedef __nv_bfloat16 bf16;
#define NOUT 4928

// ---------------- scratch (device globals; sizes in elements) ----------------
__device__ __align__(16) bf16 g_Xs5[(size_t)2048 * 6144];     // res5 aug [pos][3*2048]
__device__ __align__(16) bf16 g_W1 [(size_t)512 * 55296];     // conv1 W aug
__device__ __align__(16) bf16 g_X1 [(size_t)2048 * 3072];     // x1 aug
__device__ __align__(16) bf16 g_W2 [(size_t)1024 * 27648];    // conv2 W aug
__device__ __align__(16) bf16 g_X2 [(size_t)2048 * 3072];     // x2 aug
__device__ __align__(16) bf16 g_W3 [(size_t)4992 * 3072];     // cls1 W aug (padded)
__device__ __align__(16) bf16 g_Xr2[(size_t)131072 * 768];    // res2 aug
__device__ __align__(16) bf16 g_W4 [(size_t)64 * 6912];       // c1a W aug (padded)
__device__ float g_cls1T[(size_t)2048 * NOUT];
__device__ float g_c1aT [(size_t)131072 * 48];

// ---------------- helpers ----------------
__device__ __forceinline__ void split2(float v, bf16& h, bf16& l) {
    h = __float2bfloat16(v);
    l = __float2bfloat16(v - __bfloat162float(h));
}
__device__ __forceinline__ unsigned pkb(bf16 a, bf16 b) {
    return (unsigned)__bfloat16_as_ushort(a) | ((unsigned)__bfloat16_as_ushort(b) << 16);
}
__device__ __forceinline__ unsigned s2u(const void* p) {
    return (unsigned)__cvta_generic_to_shared(p);
}
__device__ __forceinline__ void cpa16(unsigned d, const void* s, unsigned sz) {
    asm volatile("cp.async.ca.shared.global [%0], [%1], 16, %2;" :: "r"(d), "l"(s), "r"(sz));
}
__device__ __forceinline__ void cpa_commit() {
    asm volatile("cp.async.commit_group;" ::: "memory");
}
template<int N> __device__ __forceinline__ void cpa_wait() {
    asm volatile("cp.async.wait_group %0;" :: "n"(N) : "memory");
}
__device__ __forceinline__ void ldm4(unsigned* r, unsigned a) {
    asm volatile("ldmatrix.sync.aligned.m8n8.x4.shared.b16 {%0,%1,%2,%3}, [%4];"
        : "=r"(r[0]), "=r"(r[1]), "=r"(r[2]), "=r"(r[3]) : "r"(a));
}
__device__ __forceinline__ void mma16816(float* d, const unsigned* a, const unsigned* b) {
    asm volatile("mma.sync.aligned.m16n8k16.row.col.f32.bf16.bf16.f32 "
        "{%0,%1,%2,%3}, {%4,%5,%6,%7}, {%8,%9}, {%0,%1,%2,%3};"
        : "+f"(d[0]), "+f"(d[1]), "+f"(d[2]), "+f"(d[3])
        : "r"(a[0]), "r"(a[1]), "r"(a[2]), "r"(a[3]), "r"(b[0]), "r"(b[1]));
}

// =====================================================================
// HMMA GEMM, 8 warps as 4(m) x 2(n), warp tile (BM/4)x(BN/2), BK=32,
// 3-stage cp.async pipeline, one __syncthreads per K-chunk.
// SMEM rows 80B stride => conflict-free ldmatrix.
// =====================================================================
template<int BM, int BN, bool CONV3>
__global__ __launch_bounds__(256) void gemm_mma(
    const bf16* __restrict__ A, const bf16* __restrict__ B,
    int C3, int imh, int imw, int nk, int Kb,
    int epi, int nvalid,
    const float* __restrict__ scale, const float* __restrict__ shift,
    const float* __restrict__ bias,
    bf16* __restrict__ Oaug, int outc,
    float* __restrict__ Of, int ofc)
{
    constexpr int WM = BM / 4, WN = BN / 2;
    constexpr int MT = WM / 16;       // A frags / m-subtiles
    constexpr int NT = WN / 8;        // n-subtiles
    constexpr int NF = WN / 16;       // B frags
    constexpr int AJ = BM / 64;       // A 16B-vectors per thread
    constexpr int BJ = BN / 64;
    constexpr int ABYTES = BM * 80, STG = (BM + BN) * 80;

    extern __shared__ __align__(16) char sm[];
    const int tid = threadIdx.x;
    const int nb = blockIdx.x, mtile = blockIdx.y;
    const int warp = tid >> 5, lane = tid & 31;
    const int m0 = (warp >> 1) * WM, n0 = (warp & 1) * WN;
    const unsigned sbase = s2u(sm);
    const int imgpix = imh * imw;
    const int vec = tid & 3;

    int arow[AJ], ay[AJ], ax[AJ], apb[AJ];
#pragma unroll
    for (int j = 0; j < AJ; j++) {
        arow[j] = (tid >> 2) + j * 64;
        int g = mtile * BM + arow[j];
        if (CONV3) {
            int bb = g / imgpix, lp = g - bb * imgpix;
            ay[j] = lp / imw; ax[j] = lp - ay[j] * imw; apb[j] = bb * imgpix;
        } else { ay[j] = 0; ax[j] = 0; apb[j] = g; }
    }

    auto load_chunk = [&](int kc, int st) {
        unsigned Ab = sbase + st * STG;
        unsigned Bb = Ab + ABYTES;
        int k0 = kc * 32;
        int dy = 0, dx = 0, cb = k0;
        if (CONV3) {
            int rk = k0 / C3; cb = k0 - rk * C3;
            int r3 = rk / 3; dy = r3 - 1; dx = rk - r3 * 3 - 1;
        }
#pragma unroll
        for (int j = 0; j < AJ; j++) {
            const bf16* src;
            unsigned sz = 16;
            if (CONV3) {
                int y2 = ay[j] + dy, x2 = ax[j] + dx;
                bool v = ((unsigned)y2 < (unsigned)imh) && ((unsigned)x2 < (unsigned)imw);
                src = A + (size_t)(apb[j] + y2 * imw + x2) * C3 + cb + vec * 8;
                if (!v) { src = A; sz = 0; }
            } else {
                src = A + (size_t)apb[j] * C3 + k0 + vec * 8;
            }
            cpa16(Ab + arow[j] * 80 + vec * 16, src, sz);
        }
#pragma unroll
        for (int j = 0; j < BJ; j++) {
            int row = (tid >> 2) + j * 64;
            cpa16(Bb + row * 80 + vec * 16,
                  B + (size_t)(nb * BN + row) * Kb + k0 + vec * 8, 16);
        }
    };

    float acc[MT][NT][4];
#pragma unroll
    for (int a = 0; a < MT; a++)
#pragma unroll
        for (int b2 = 0; b2 < NT; b2++)
#pragma unroll
            for (int c = 0; c < 4; c++) acc[a][b2][c] = 0.f;

    auto compute = [&](int st) {
        unsigned Ab = sbase + st * STG;
        unsigned Bb = Ab + ABYTES;
#pragma unroll
        for (int step = 0; step < 2; step++) {
            unsigned af[MT][4], bfr[NF][4];
            {
                int ch = step * 2 + (lane >> 4);
#pragma unroll
                for (int i = 0; i < MT; i++)
                    ldm4(af[i], Ab + (m0 + 16 * i + (lane & 15)) * 80 + ch * 16);
            }
            {
                int rr = (lane & 7) + ((lane >> 4) << 3);
                int ch = step * 2 + ((lane >> 3) & 1);
#pragma unroll
                for (int i = 0; i < NF; i++)
                    ldm4(bfr[i], Bb + (n0 + 16 * i + rr) * 80 + ch * 16);
            }
#pragma unroll
            for (int mt = 0; mt < MT; mt++)
#pragma unroll
                for (int nt = 0; nt < NT; nt++)
                    mma16816(acc[mt][nt], af[mt], &bfr[nt >> 1][(nt & 1) * 2]);
        }
    };

    load_chunk(0, 0);
    cpa_commit();
    if (nk > 1) load_chunk(1, 1);
    cpa_commit();
    int st2 = 2;
    for (int kc = 0; kc < nk; kc++) {
        cpa_wait<1>();
        __syncthreads();
        if (kc + 2 < nk) {
            load_chunk(kc + 2, st2);
            if (++st2 == 3) st2 = 0;
        }
        cpa_commit();
        compute(kc % 3);
    }

    // ---- epilogue ----
#pragma unroll
    for (int mt = 0; mt < MT; mt++)
#pragma unroll
        for (int nt = 0; nt < NT; nt++) {
            float* d = acc[mt][nt];
            int row = mtile * BM + m0 + mt * 16 + (lane >> 2);
            int col = nb * BN + n0 + nt * 8 + (lane & 3) * 2;
#pragma unroll
            for (int h = 0; h < 2; h++) {
                int r = row + h * 8;
                float v0 = d[h * 2 + 0], v1 = d[h * 2 + 1];
                if (epi == 0) {
                    v0 = fmaxf(fmaf(v0, scale[col], shift[col]), 0.f);
                    v1 = fmaxf(fmaf(v1, scale[col + 1], shift[col + 1]), 0.f);
                    bf16 h0, l0, h1, l1; split2(v0, h0, l0); split2(v1, h1, l1);
                    size_t base = (size_t)r * 3 * outc + col;
                    *(unsigned*)(Oaug + base) = pkb(h0, h1);
                    *(unsigned*)(Oaug + base + outc) = pkb(l0, l1);
                    *(unsigned*)(Oaug + base + 2 * outc) = pkb(h0, h1);
                } else if (epi == 1) {
                    if (col < nvalid) {
                        float2 o = make_float2(v0 + bias[col], v1 + bias[col + 1]);
                        *(float2*)(Of + (size_t)r * ofc + col) = o;
                    }
                } else {
                    if (col < nvalid) {
                        float2 o;
                        o.x = fmaxf(fmaf(v0, scale[col], shift[col]), 0.f);
                        o.y = fmaxf(fmaf(v1, scale[col + 1], shift[col + 1]), 0.f);
                        *(float2*)(Of + (size_t)r * ofc + col) = o;
                    }
                }
            }
        }
}

// ---------------- prep: NCHW fp32 -> [pos][3C] augmented bf16 ----------------
__global__ __launch_bounds__(256) void split_aug(
    const float* __restrict__ in, bf16* __restrict__ out, int C, int HW)
{
    __shared__ float t[32][33];
    const int b = blockIdx.z, c0 = blockIdx.y * 32, p0 = blockIdx.x * 32;
    const int tx = threadIdx.x & 31, ty = threadIdx.x >> 5;
#pragma unroll
    for (int r = 0; r < 4; r++)
        t[ty + 8 * r][tx] = in[((size_t)b * C + c0 + ty + 8 * r) * HW + p0 + tx];
    __syncthreads();
#pragma unroll
    for (int r = 0; r < 4; r++) {
        int p = p0 + ty + 8 * r;
        float v = t[tx][ty + 8 * r];
        bf16 h, l; split2(v, h, l);
        size_t o = ((size_t)b * HW + p) * 3 * C + c0 + tx;
        out[o] = h; out[o + C] = l; out[o + 2 * C] = h;
    }
}

// ---------------- prep: conv weight OIHW -> [oc][tap][3C] augmented ----------------
__global__ __launch_bounds__(256) void wsplit_conv_aug(
    const float* __restrict__ w, bf16* __restrict__ out, int C, int OC)
{
    int idx = blockIdx.x * 256 + threadIdx.x;
    int oc = idx / (9 * C); int rem = idx - oc * 9 * C;
    int tap = rem / C; int c = rem - tap * C;
    float v = (oc < OC) ? w[((size_t)oc * C + c) * 9 + tap] : 0.f;
    bf16 h, l; split2(v, h, l);
    size_t base = (size_t)oc * (27 * C) + (size_t)tap * 3 * C;
    out[base + c] = h; out[base + C + c] = h; out[base + 2 * C + c] = l;
}

// ---------------- merged small prep: c1a W aug + cls1 W aug ----------------
__global__ __launch_bounds__(256) void wsplit_small(
    const float* __restrict__ aw, const float* __restrict__ c1w,
    bf16* __restrict__ W4, bf16* __restrict__ W3)
{
    const int N4 = 64 * 9 * 256;
    int idx = blockIdx.x * 256 + threadIdx.x;
    if (idx < N4) {
        int oc = idx / (9 * 256); int rem = idx - oc * 9 * 256;
        int tap = rem / 256; int c = rem - tap * 256;
        float v = (oc < 48) ? aw[((size_t)oc * 256 + c) * 9 + tap] : 0.f;
        bf16 h, l; split2(v, h, l);
        size_t base = (size_t)oc * (27 * 256) + (size_t)tap * 768;
        W4[base + c] = h; W4[base + 256 + c] = h; W4[base + 512 + c] = l;
    } else {
        int i2 = idx - N4;
        if (i2 < 4992 * 1024) {
            int oc = i2 >> 10, c = i2 & 1023;
            float v = (oc < NOUT) ? c1w[(size_t)oc * 1024 + c] : 0.f;
            bf16 h, l; split2(v, h, l);
            size_t base = (size_t)oc * 3072;
            W3[base + c] = h; W3[base + 1024 + c] = h; W3[base + 2048 + c] = l;
        }
    }
}

// ---------------- global pool: mean of ch 0..511 -> aug ch 512..1023 ----------------
__global__ __launch_bounds__(512) void gp2(bf16* __restrict__ X)
{
    const int b = blockIdx.x, c = threadIdx.x;   // c in [0,512)
    float s = 0.f;
    for (int p = 0; p < 256; p++) {
        size_t i = ((size_t)(b * 256 + p)) * 3072 + c;
        s += __bfloat162float(X[i]) + __bfloat162float(X[i + 1024]);
    }
    float m = s * (1.f / 256.f);
    bf16 h, l; split2(m, h, l);
    for (int p = 0; p < 256; p++) {
        size_t base = ((size_t)(b * 256 + p)) * 3072 + 512 + c;
        X[base] = h; X[base + 1024] = l; X[base + 2048] = h;
    }
}

// ---------------- fused: c1b + coord + cat-BN + 3-layer dynamic MLP ----------------
__global__ __launch_bounds__(256) void fused_final(
    const float* __restrict__ cls1T, const float* __restrict__ c1aT,
    const float* __restrict__ c1b_w, const float* __restrict__ c1b_b,
    const float* __restrict__ cat_scale, const float* __restrict__ cat_shift,
    float* __restrict__ out)
{
    const int b = blockIdx.y, lpos = blockIdx.x;
    const int ly = lpos >> 4, lx = lpos & 15;
    const int tid = threadIdx.x;
    const int px = tid & 63, q = tid >> 6;
    const int py = px >> 3, pxx = px & 7;

    __shared__ float sP[NOUT];
    __shared__ float sA[48 * 64];
    __shared__ float sI[18 * 64];
    __shared__ float sH0[16 * 64];
    __shared__ float sH1[16 * 64];
    __shared__ float sWb[768 + 16];

    const float* pp = cls1T + (size_t)(b * 256 + lpos) * NOUT;
    for (int i = tid; i < NOUT; i += 256) sP[i] = pp[i];
    for (int i = tid; i < 48 * 64; i += 256) {
        int p = i / 48, ch = i - p * 48;
        int yy = ly * 8 + (p >> 3), xx = lx * 8 + (p & 7);
        sA[ch * 64 + p] = c1aT[((size_t)b * 16384 + yy * 128 + xx) * 48 + ch];
    }
    for (int i = tid; i < 768; i += 256) sWb[i] = c1b_w[i];
    if (tid < 16) sWb[768 + tid] = c1b_b[tid];
    __syncthreads();

#pragma unroll
    for (int jj = 0; jj < 4; jj++) {
        int j = q * 4 + jj;
        float s = sWb[768 + j];
#pragma unroll
        for (int c = 0; c < 48; c++)
            s = fmaf(sA[c * 64 + px], sWb[j * 48 + c], s);
        sI[(2 + j) * 64 + px] = fmaf(s, cat_scale[2 + j], cat_shift[2 + j]);
    }
    if (q == 0) {
        sI[px]      = fmaf((float)pxx * 0.125f, cat_scale[0], cat_shift[0]);
        sI[64 + px] = fmaf((float)py  * 0.125f, cat_scale[1], cat_shift[1]);
    }
    __syncthreads();

#pragma unroll
    for (int jj = 0; jj < 4; jj++) {
        int o = q * 4 + jj;
        float s = sP[288 + o];
#pragma unroll
        for (int c = 0; c < 18; c++)
            s = fmaf(sP[o * 18 + c], sI[c * 64 + px], s);
        sH0[o * 64 + px] = fmaxf(s, 0.f);
    }
    __syncthreads();

#pragma unroll
    for (int jj = 0; jj < 4; jj++) {
        int o = q * 4 + jj;
        float s = sP[560 + o];
#pragma unroll
        for (int c = 0; c < 16; c++)
            s = fmaf(sP[304 + o * 16 + c], sH0[c * 64 + px], s);
        sH1[o * 64 + px] = fmaxf(s, 0.f);
    }
    __syncthreads();

    float hr[16];
#pragma unroll
    for (int c = 0; c < 16; c++) hr[c] = sH1[c * 64 + px];
    const int y = ly * 8 + py, x = lx * 8 + pxx;
    float* ob = out + (((size_t)b * 256) << 14) + (y << 7) + x;
#pragma unroll 4
    for (int oo = 0; oo < 64; oo++) {
        int o = q * 64 + oo;
        float s = sP[4672 + o];
#pragma unroll
        for (int c = 0; c < 16; c++)
            s = fmaf(sP[576 + o * 16 + c], hr[c], s);
        ob[(size_t)o << 14] = s;
    }
}

// ---------------- host launcher ----------------
extern "C" void kernel_launch(void* const* d_in, const int* in_sizes, int n_in,
                              void* d_out, int out_size)
{
    const float* res5 = (const float*)d_in[0];
    const float* res2 = (const float*)d_in[1];
    const float* bw   = (const float*)d_in[2];
    const float* bn1s = (const float*)d_in[3];
    const float* bn1h = (const float*)d_in[4];
    const float* c0w  = (const float*)d_in[5];
    const float* bn2s = (const float*)d_in[6];
    const float* bn2h = (const float*)d_in[7];
    const float* c1w  = (const float*)d_in[8];
    const float* c1b  = (const float*)d_in[9];
    const float* aw   = (const float*)d_in[10];
    const float* bn3s = (const float*)d_in[11];
    const float* bn3h = (const float*)d_in[12];
    const float* bw2  = (const float*)d_in[13];
    const float* bb2  = (const float*)d_in[14];
    const float* cats = (const float*)d_in[15];
    const float* cath = (const float*)d_in[16];
    float* out = (float*)d_out;

    bf16 *Xs5, *W1, *X1, *W2, *X2, *W3, *Xr2, *W4;
    float *cls1T, *c1aT;
    cudaGetSymbolAddress((void**)&Xs5, g_Xs5);
    cudaGetSymbolAddress((void**)&W1,  g_W1);
    cudaGetSymbolAddress((void**)&X1,  g_X1);
    cudaGetSymbolAddress((void**)&W2,  g_W2);
    cudaGetSymbolAddress((void**)&X2,  g_X2);
    cudaGetSymbolAddress((void**)&W3,  g_W3);
    cudaGetSymbolAddress((void**)&Xr2, g_Xr2);
    cudaGetSymbolAddress((void**)&W4,  g_W4);
    cudaGetSymbolAddress((void**)&cls1T, g_cls1T);
    cudaGetSymbolAddress((void**)&c1aT,  g_c1aT);

    const int SM_C1 = (128 + 64) * 80 * 3;    // 46080
    const int SM_BB = (128 + 128) * 80 * 3;   // 61440
    const int SM_C4 = (256 + 64) * 80 * 3;    // 76800
    cudaFuncSetAttribute(gemm_mma<128, 64, true>,   cudaFuncAttributeMaxDynamicSharedMemorySize, SM_C1);
    cudaFuncSetAttribute(gemm_mma<128, 128, true>,  cudaFuncAttributeMaxDynamicSharedMemorySize, SM_BB);
    cudaFuncSetAttribute(gemm_mma<128, 128, false>, cudaFuncAttributeMaxDynamicSharedMemorySize, SM_BB);
    cudaFuncSetAttribute(gemm_mma<256, 64, true>,   cudaFuncAttributeMaxDynamicSharedMemorySize, SM_C4);

    // ---- prep (5 launches so launch #6 = conv1 GEMM for ncu) ----
    split_aug<<<dim3(8, 64, 8), 256>>>(res5, Xs5, 2048, 256);
    split_aug<<<dim3(512, 8, 8), 256>>>(res2, Xr2, 256, 16384);
    wsplit_conv_aug<<<(512 * 9 * 2048) / 256, 256>>>(bw, W1, 2048, 512);
    wsplit_conv_aug<<<(1024 * 9 * 1024) / 256, 256>>>(c0w, W2, 1024, 1024);
    wsplit_small<<<(64 * 9 * 256 + 4992 * 1024 + 255) / 256, 256>>>(aw, c1w, W4, W3);

    // ---- conv1: [2048 x 55296] * [512 x 55296] -> X1 aug ch 0..511 ----
    gemm_mma<128, 64, true><<<dim3(8, 16), 256, SM_C1>>>(
        Xs5, W1, 6144, 16, 16, 1728, 55296, 0, 512,
        bn1s, bn1h, nullptr, X1, 1024, nullptr, 0);
    // ---- global pool broadcast into aug ch 512..1023 ----
    gp2<<<8, 512>>>(X1);
    // ---- conv2: [2048 x 27648] * [1024 x 27648] -> X2 aug ----
    gemm_mma<128, 128, true><<<dim3(8, 16), 256, SM_BB>>>(
        X1, W2, 3072, 16, 16, 864, 27648, 0, 1024,
        bn2s, bn2h, nullptr, X2, 1024, nullptr, 0);
    // ---- cls1: [2048 x 3072] * [4992 x 3072] -> cls1T fp32 ----
    gemm_mma<128, 128, false><<<dim3(39, 16), 256, SM_BB>>>(
        X2, W3, 3072, 16, 16, 96, 3072, 1, NOUT,
        nullptr, nullptr, c1b, nullptr, 0, cls1T, NOUT);
    // ---- c1a: [131072 x 6912] * [64 x 6912] -> c1aT fp32 ----
    gemm_mma<256, 64, true><<<dim3(1, 512), 256, SM_C4>>>(
        Xr2, W4, 768, 128, 128, 216, 6912, 2, 48,
        bn3s, bn3h, nullptr, nullptr, 0, c1aT, 48);
    // ---- fused tail ----
    fused_final<<<dim3(256, 8), 256>>>(cls1T, c1aT, bw2, bb2, cats, cath, out);
}